// round 3
// baseline (speedup 1.0000x reference)
#include <cuda_runtime.h>

typedef unsigned long long u64;

#define NCH_ 28            // input channels per cc-group: 4*4+12
#define XROW 40            // 8-word left halo + 32 words
#define XS_WORDS (NCH_ * 32 * XROW)          // 35840
#define W_WORDS  (16 * 9 * 9 * 8)            // 10368
#define SMEM_BYTES ((XS_WORDS + W_WORDS) * 4)  // 184832

__device__ __forceinline__ u64 pack2(float a, float b) {
    u64 r; asm("mov.b64 %0, {%1, %2};" : "=l"(r) : "f"(a), "f"(b)); return r;
}
__device__ __forceinline__ u64 fma2(u64 a, u64 b, u64 c) {
    u64 d; asm("fma.rn.f32x2 %0, %1, %2, %3;" : "=l"(d) : "l"(a), "l"(b), "l"(c)); return d;
}
__device__ __forceinline__ void unpack2(u64 v, float& lo, float& hi) {
    asm("mov.b64 {%0, %1}, %2;" : "=f"(lo), "=f"(hi) : "l"(v));
}

// out[b, n*32+cc, h, w] = sum_{c<16, kh<9, kw<9}
//     x[b, (4cc-c)&127, (h-kh)&31, (w-kw)&31] * W[n, c, kh, kw]
// Block: (b, group of 4 cc). 512 threads; each thread: one h, two w (w0,w0+1),
// all 8 n, 4 cc in two passes of 2 cc (register pressure).
__global__ __launch_bounds__(512, 1)
void fconv_kernel(const float* __restrict__ x,
                  const float* __restrict__ w,
                  float* __restrict__ out)
{
    extern __shared__ float smem[];
    float* xs  = smem;                 // [28][32][40] (halo rows)
    float* wsm = smem + XS_WORDS;      // [c=16][kh=9][kw=9][n=8]

    const int t   = threadIdx.x;
    const int ccg = blockIdx.x;        // 0..7
    const int b   = blockIdx.y;        // 0..31
    const int cc0 = ccg * 4;
    const int ch_base = (4 * cc0 + 113) & 127;    // (4*cc0 - 15) mod 128

    // ---- stage x (main body, coalesced) ----
    const float* xb = x + (size_t)b * 128 * 1024;
    for (int idx = t; idx < NCH_ * 1024; idx += 512) {
        int ci = idx >> 10, p = idx & 1023;
        int cin = (ch_base + ci) & 127;
        xs[ci * (32 * XROW) + (p >> 5) * XROW + 8 + (p & 31)] = xb[cin * 1024 + p];
    }
    // ---- stage x halo: rowbuf[k<8] = x[.., 24+k] ----
    for (int idx = t; idx < NCH_ * 32 * 8; idx += 512) {
        int ci = idx >> 8, r = idx & 255;
        int hh = r >> 3, k = r & 7;
        int cin = (ch_base + ci) & 127;
        xs[ci * (32 * XROW) + hh * XROW + k] = xb[cin * 1024 + hh * 32 + 24 + k];
    }
    // ---- stage weights transposed: wsm[((c*9+kh)*9+kw)*8 + n] ----
    for (int idx = t; idx < 16 * 81 * 8; idx += 512) {
        int n = idx & 7, r = idx >> 3;
        wsm[idx] = w[n * 1296 + r];
    }
    __syncthreads();

    // thread mapping: half-warp shares h (conflict-free LDS.64 / coalesced STG)
    const int lane = t & 31;
    const int wp   = t >> 5;
    const int h    = wp * 2 + (lane >> 4);
    const int w0   = (lane & 15) * 2;

    #pragma unroll 1
    for (int jp = 0; jp < 4; jp += 2) {
        u64 acc[2][4][2];
        #pragma unroll
        for (int dj = 0; dj < 2; ++dj)
            #pragma unroll
            for (int np = 0; np < 4; ++np) {
                acc[dj][np][0] = 0ull; acc[dj][np][1] = 0ull;
            }

        #pragma unroll 1
        for (int c = 0; c < 16; ++c) {
            #pragma unroll 1
            for (int kh = 0; kh < 9; ++kh) {
                const int hh = (h - kh) & 31;

                // hoist 36 weight pairs via 18 LDS.128
                u64 wr[36];
                const ulonglong2* wp2 =
                    (const ulonglong2*)&wsm[(c * 9 + kh) * 72];
                #pragma unroll
                for (int q = 0; q < 18; ++q) {
                    ulonglong2 v = wp2[q];
                    wr[2 * q] = v.x; wr[2 * q + 1] = v.y;
                }

                #pragma unroll
                for (int dj = 0; dj < 2; ++dj) {
                    const int j = jp + dj;
                    const float* row =
                        &xs[(15 - c + 4 * j) * (32 * XROW) + hh * XROW + w0];
                    // xp[i] = x[(w0 - 8 + i) & 31], i = 0..9, via 5 LDS.64
                    u64 xp[10];
                    #pragma unroll
                    for (int q = 0; q < 5; ++q) {
                        u64 raw = *(const u64*)(row + 2 * q);
                        float lo, hi; unpack2(raw, lo, hi);
                        xp[2 * q]     = pack2(lo, lo);
                        xp[2 * q + 1] = pack2(hi, hi);
                    }
                    #pragma unroll
                    for (int kw = 0; kw < 9; ++kw) {
                        #pragma unroll
                        for (int np = 0; np < 4; ++np) {
                            acc[dj][np][0] = fma2(xp[8 - kw], wr[kw * 4 + np], acc[dj][np][0]);
                            acc[dj][np][1] = fma2(xp[9 - kw], wr[kw * 4 + np], acc[dj][np][1]);
                        }
                    }
                }
            }
        }

        // ---- store: channel = n*32 + cc, float2 over (w0, w0+1) ----
        #pragma unroll
        for (int dj = 0; dj < 2; ++dj) {
            const int cc = cc0 + jp + dj;
            #pragma unroll
            for (int np = 0; np < 4; ++np) {
                float a0n0, a0n1, a1n0, a1n1;
                unpack2(acc[dj][np][0], a0n0, a0n1);   // w0:   n=2np, 2np+1
                unpack2(acc[dj][np][1], a1n0, a1n1);   // w0+1: n=2np, 2np+1
                size_t base = ((size_t)b * 256 + cc) * 1024 + h * 32 + w0;
                float2 s0 = make_float2(a0n0, a1n0);
                float2 s1 = make_float2(a0n1, a1n1);
                *(float2*)&out[base + (size_t)(2 * np)     * 32 * 1024] = s0;
                *(float2*)&out[base + (size_t)(2 * np + 1) * 32 * 1024] = s1;
            }
        }
    }
}

extern "C" void kernel_launch(void* const* d_in, const int* in_sizes, int n_in,
                              void* d_out, int out_size)
{
    const float* x = (const float*)d_in[0];   // (32,128,32,32) f32
    const float* w = (const float*)d_in[1];   // (8,16,9,9) f32
    float* out = (float*)d_out;               // (32,256,32,32) f32

    cudaFuncSetAttribute(fconv_kernel,
                         cudaFuncAttributeMaxDynamicSharedMemorySize, SMEM_BYTES);
    dim3 grid(8, 32);
    fconv_kernel<<<grid, 512, SMEM_BYTES>>>(x, w, out);
}

// round 4
// speedup vs baseline: 1.0022x; 1.0022x over previous
#include <cuda_runtime.h>

typedef unsigned long long u64;

#define NCH_ 28            // input channels per cc-group: 4*4+12
#define XROW 40            // 8-word left halo + 32 words
#define XS_WORDS (NCH_ * 32 * XROW)          // 35840
#define W_WORDS  (16 * 9 * 9 * 8)            // 10368
#define SMEM_BYTES ((XS_WORDS + W_WORDS) * 4)  // 184832

__device__ __forceinline__ u64 pack2(float a, float b) {
    u64 r; asm("mov.b64 %0, {%1, %2};" : "=l"(r) : "f"(a), "f"(b)); return r;
}
__device__ __forceinline__ u64 fma2(u64 a, u64 b, u64 c) {
    u64 d; asm("fma.rn.f32x2 %0, %1, %2, %3;" : "=l"(d) : "l"(a), "l"(b), "l"(c)); return d;
}
__device__ __forceinline__ void unpack2(u64 v, float& lo, float& hi) {
    asm("mov.b64 {%0, %1}, %2;" : "=f"(lo), "=f"(hi) : "l"(v));
}

// out[b, n*32+cc, h, w] = sum_{c<16, kh<9, kw<9}
//     x[b, (4cc-c)&127, (h-kh)&31, (w-kw)&31] * W[n, c, kh, kw]
// Block: (b, group of 4 cc). 512 threads; each thread: one h, two w (w0,w0+1),
// all 8 n, 4 cc in two passes of 2 cc (register pressure).
__global__ __launch_bounds__(512, 1)
void fconv_kernel(const float* __restrict__ x,
                  const float* __restrict__ w,
                  float* __restrict__ out)
{
    extern __shared__ float smem[];
    float* xs  = smem;                 // [28][32][40] (halo rows)
    float* wsm = smem + XS_WORDS;      // [c=16][kh=9][kw=9][n=8]

    const int t   = threadIdx.x;
    const int ccg = blockIdx.x;        // 0..7
    const int b   = blockIdx.y;        // 0..31
    const int cc0 = ccg * 4;
    const int ch_base = (4 * cc0 + 113) & 127;    // (4*cc0 - 15) mod 128

    // ---- stage x (main body, coalesced) ----
    const float* xb = x + (size_t)b * 128 * 1024;
    for (int idx = t; idx < NCH_ * 1024; idx += 512) {
        int ci = idx >> 10, p = idx & 1023;
        int cin = (ch_base + ci) & 127;
        xs[ci * (32 * XROW) + (p >> 5) * XROW + 8 + (p & 31)] = xb[cin * 1024 + p];
    }
    // ---- stage x halo: rowbuf[k<8] = x[.., 24+k] ----
    for (int idx = t; idx < NCH_ * 32 * 8; idx += 512) {
        int ci = idx >> 8, r = idx & 255;
        int hh = r >> 3, k = r & 7;
        int cin = (ch_base + ci) & 127;
        xs[ci * (32 * XROW) + hh * XROW + k] = xb[cin * 1024 + hh * 32 + 24 + k];
    }
    // ---- stage weights transposed: wsm[((c*9+kh)*9+kw)*8 + n] ----
    for (int idx = t; idx < 16 * 81 * 8; idx += 512) {
        int n = idx & 7, r = idx >> 3;
        wsm[idx] = w[n * 1296 + r];
    }
    __syncthreads();

    // thread mapping: half-warp shares h (conflict-free LDS.64 / coalesced STG)
    const int lane = t & 31;
    const int wp   = t >> 5;
    const int h    = wp * 2 + (lane >> 4);
    const int w0   = (lane & 15) * 2;

    #pragma unroll 1
    for (int jp = 0; jp < 4; jp += 2) {
        u64 acc[2][4][2];
        #pragma unroll
        for (int dj = 0; dj < 2; ++dj)
            #pragma unroll
            for (int np = 0; np < 4; ++np) {
                acc[dj][np][0] = 0ull; acc[dj][np][1] = 0ull;
            }

        #pragma unroll 1
        for (int c = 0; c < 16; ++c) {
            #pragma unroll 1
            for (int kh = 0; kh < 9; ++kh) {
                const int hh = (h - kh) & 31;

                // hoist 36 weight pairs via 18 LDS.128
                u64 wr[36];
                const ulonglong2* wp2 =
                    (const ulonglong2*)&wsm[(c * 9 + kh) * 72];
                #pragma unroll
                for (int q = 0; q < 18; ++q) {
                    ulonglong2 v = wp2[q];
                    wr[2 * q] = v.x; wr[2 * q + 1] = v.y;
                }

                #pragma unroll
                for (int dj = 0; dj < 2; ++dj) {
                    const int j = jp + dj;
                    const float* row =
                        &xs[(15 - c + 4 * j) * (32 * XROW) + hh * XROW + w0];
                    // xp[i] = x[(w0 - 8 + i) & 31], i = 0..9, via 5 LDS.64
                    u64 xp[10];
                    #pragma unroll
                    for (int q = 0; q < 5; ++q) {
                        u64 raw = *(const u64*)(row + 2 * q);
                        float lo, hi; unpack2(raw, lo, hi);
                        xp[2 * q]     = pack2(lo, lo);
                        xp[2 * q + 1] = pack2(hi, hi);
                    }
                    #pragma unroll
                    for (int kw = 0; kw < 9; ++kw) {
                        #pragma unroll
                        for (int np = 0; np < 4; ++np) {
                            acc[dj][np][0] = fma2(xp[8 - kw], wr[kw * 4 + np], acc[dj][np][0]);
                            acc[dj][np][1] = fma2(xp[9 - kw], wr[kw * 4 + np], acc[dj][np][1]);
                        }
                    }
                }
            }
        }

        // ---- store: channel = n*32 + cc, float2 over (w0, w0+1) ----
        #pragma unroll
        for (int dj = 0; dj < 2; ++dj) {
            const int cc = cc0 + jp + dj;
            #pragma unroll
            for (int np = 0; np < 4; ++np) {
                float a0n0, a0n1, a1n0, a1n1;
                unpack2(acc[dj][np][0], a0n0, a0n1);   // w0:   n=2np, 2np+1
                unpack2(acc[dj][np][1], a1n0, a1n1);   // w0+1: n=2np, 2np+1
                size_t base = ((size_t)b * 256 + cc) * 1024 + h * 32 + w0;
                float2 s0 = make_float2(a0n0, a1n0);
                float2 s1 = make_float2(a0n1, a1n1);
                *(float2*)&out[base + (size_t)(2 * np)     * 32 * 1024] = s0;
                *(float2*)&out[base + (size_t)(2 * np + 1) * 32 * 1024] = s1;
            }
        }
    }
}

extern "C" void kernel_launch(void* const* d_in, const int* in_sizes, int n_in,
                              void* d_out, int out_size)
{
    const float* x = (const float*)d_in[0];   // (32,128,32,32) f32
    const float* w = (const float*)d_in[1];   // (8,16,9,9) f32
    float* out = (float*)d_out;               // (32,256,32,32) f32

    cudaFuncSetAttribute(fconv_kernel,
                         cudaFuncAttributeMaxDynamicSharedMemorySize, SMEM_BYTES);
    dim3 grid(8, 32);
    fconv_kernel<<<grid, 512, SMEM_BYTES>>>(x, w, out);
}

// round 6
// speedup vs baseline: 2.2447x; 2.2399x over previous
#include <cuda_runtime.h>
#include <cstdint>
typedef uint32_t u32;

#define XP 1288                       // channel pitch in words (8 mod 32 -> conflict-free)
#define BW_OFF (28 * XP)              // 36064 words: start of B table
#define SMEM_WORDS (BW_OFF + 10368)
#define SMEM_BYTES (SMEM_WORDS * 4)   // 185728 B

__device__ __forceinline__ u32 f2t(float f) {
    u32 r; asm("cvt.rna.tf32.f32 %0, %1;" : "=r"(r) : "f"(f)); return r;
}

__device__ __forceinline__ void mma8(float& d0, float& d1, float& d2, float& d3,
                                     u32 a0, u32 a1, u32 a2, u32 a3, u32 b0, u32 b1) {
    asm("mma.sync.aligned.m16n8k8.row.col.f32.tf32.tf32.f32 "
        "{%0,%1,%2,%3},{%4,%5,%6,%7},{%8,%9},{%0,%1,%2,%3};"
        : "+f"(d0), "+f"(d1), "+f"(d2), "+f"(d3)
        : "r"(a0), "r"(a1), "r"(a2), "r"(a3), "r"(b0), "r"(b1));
}

// out[b, n*32+cc, h, w] = sum_{c<16,kh,kw} x[b,(4cc-c)&127,(h-kh)&31,(w-kw)&31] * W[n,c,kh,kw]
// CTA = (g, b): cc = 4g..4g+3, input channel union = 28 channels [16g-15, 16g+12].
// Warp = one h row per pass (16 warps x 2 passes). mma: M=16 w-positions (2 tiles),
// N=8 filters, K=16 channels per jc in 2 k8 steps; 81 taps accumulate in registers.
__global__ __launch_bounds__(512, 1)
void fconv_mma(const float* __restrict__ x, const float* __restrict__ w,
               float* __restrict__ out)
{
    extern __shared__ u32 sm[];
    u32* xs = sm;                 // [c<28][h<32][40], pitch XP per channel, w-halo 8 left
    u32* Bs = sm + BW_OFF;        // [tap<81][k<16][n<8]

    const int t = threadIdx.x, g = blockIdx.x, b = blockIdx.y;
    const int chb = (16 * g + 113) & 127;          // (16g - 15) mod 128
    const float* xb = x + (size_t)b * 131072;

    // ---- stage x as tf32, halo'd rows of 40 ----
    for (int i = t; i < 28 * 1280; i += 512) {
        int c = i / 1280, r = i % 1280, hh = r / 40, j = r % 40;
        xs[c * XP + hh * 40 + j] =
            f2t(xb[((chb + c) & 127) * 1024 + hh * 32 + ((j + 24) & 31)]);
    }
    // ---- stage B[tap][k][n] = W[n, 15-k, tap] as tf32 ----
    for (int i = t; i < 10368; i += 512) {
        int tap = i >> 7, r = i & 127, k = r >> 3, n = r & 7;
        Bs[i] = f2t(w[n * 1296 + (15 - k) * 81 + tap]);
    }
    __syncthreads();

    const int lane = t & 31, wid = t >> 5, gq = lane >> 2, tq = lane & 3;

    #pragma unroll 1
    for (int pass = 0; pass < 2; ++pass) {
        const int h = wid + 16 * pass;
        float acc[2][4][4];
        #pragma unroll
        for (int mt = 0; mt < 2; ++mt)
            #pragma unroll
            for (int jc = 0; jc < 4; ++jc)
                #pragma unroll
                for (int q = 0; q < 4; ++q) acc[mt][jc][q] = 0.f;

        #pragma unroll 1
        for (int kh = 0; kh < 9; ++kh) {
            const int row = (h - kh) & 31;
            const u32* xrow = xs + row * 40 + gq;

            // rolling per-thread windows: CH[buf][mt][j] = x[ch][row][mt*16 + gq + j - 8]
            u32 CH[2][2][17];
            #pragma unroll
            for (int ci = 0; ci < 2; ++ci) {
                const u32* p = xrow + (4 * ci + tq) * XP;
                #pragma unroll
                for (int j = 0; j < 17; ++j) { CH[ci][0][j] = p[j]; CH[ci][1][j] = p[16 + j]; }
            }

            #pragma unroll
            for (int i = 0; i < 6; ++i) {       // k8 offset o6 = 4i
                if (i > 0) {
                    const u32* p = xrow + (4 * (i + 1) + tq) * XP;
                    #pragma unroll
                    for (int j = 0; j < 17; ++j) {
                        CH[(i + 1) & 1][0][j] = p[j];
                        CH[(i + 1) & 1][1][j] = p[16 + j];
                    }
                }
                const int lob = i & 1, hib = (i + 1) & 1;
                #pragma unroll
                for (int kw = 0; kw < 9; ++kw) {
                    const int tap = kh * 9 + kw;
                    #pragma unroll
                    for (int u = 0; u < 2; ++u) {
                        // (jc, ks) pairs with 4*jc + 8*ks == 4*i
                        const int jc = (u == 0) ? i : i - 2;
                        const int ks = u;
                        if ((u == 0 && i < 4) || (u == 1 && i >= 2)) {
                            u32 b0 = Bs[tap * 128 + (8 * ks + tq) * 8 + gq];
                            u32 b1 = Bs[tap * 128 + (8 * ks + 4 + tq) * 8 + gq];
                            #pragma unroll
                            for (int mt = 0; mt < 2; ++mt)
                                mma8(acc[mt][jc][0], acc[mt][jc][1],
                                     acc[mt][jc][2], acc[mt][jc][3],
                                     CH[lob][mt][8 - kw], CH[lob][mt][16 - kw],
                                     CH[hib][mt][8 - kw], CH[hib][mt][16 - kw],
                                     b0, b1);
                        }
                    }
                }
            }
        }

        // ---- store: D row m -> w = mt*16 + m, col n -> ch = n*32 + 4g + jc ----
        #pragma unroll
        for (int mt = 0; mt < 2; ++mt)
            #pragma unroll
            for (int jc = 0; jc < 4; ++jc) {
                const int cc = 4 * g + jc;
                #pragma unroll
                for (int d = 0; d < 2; ++d) {
                    const int ch = (2 * tq + d) * 32 + cc;
                    float* ob = out + (size_t)b * 262144 + (size_t)ch * 1024
                              + h * 32 + mt * 16 + gq;
                    ob[0] = acc[mt][jc][d];        // row gq
                    ob[8] = acc[mt][jc][2 + d];    // row gq + 8
                }
            }
    }
}

extern "C" void kernel_launch(void* const* d_in, const int* in_sizes, int n_in,
                              void* d_out, int out_size)
{
    const float* x = (const float*)d_in[0];   // (32,128,32,32) f32
    const float* w = (const float*)d_in[1];   // (8,16,9,9) f32
    float* out = (float*)d_out;               // (32,256,32,32) f32

    cudaFuncSetAttribute(fconv_mma,
                         cudaFuncAttributeMaxDynamicSharedMemorySize, SMEM_BYTES);
    dim3 grid(8, 32);
    fconv_mma<<<grid, 512, SMEM_BYTES>>>(x, w, out);
}

// round 8
// speedup vs baseline: 3.0750x; 1.3699x over previous
#include <cuda_runtime.h>
#include <cstdint>
typedef uint32_t u32;
typedef unsigned long long u64;

#define XP 1288                       // channel pitch in words (≡8 mod 32, conflict-free)
#define BW_OFF (28 * XP)              // 36064 words: start of B pair table
#define SMEM_WORDS (BW_OFF + 10368)
#define SMEM_BYTES (SMEM_WORDS * 4)   // 185728 B

__device__ __forceinline__ u32 f2t(float f) {
    u32 r; asm("cvt.rna.tf32.f32 %0, %1;" : "=r"(r) : "f"(f)); return r;
}

__device__ __forceinline__ void mma8(float& d0, float& d1, float& d2, float& d3,
                                     u32 a0, u32 a1, u32 a2, u32 a3, u32 b0, u32 b1) {
    asm("mma.sync.aligned.m16n8k8.row.col.f32.tf32.tf32.f32 "
        "{%0,%1,%2,%3},{%4,%5,%6,%7},{%8,%9},{%0,%1,%2,%3};"
        : "+f"(d0), "+f"(d1), "+f"(d2), "+f"(d3)
        : "r"(a0), "r"(a1), "r"(a2), "r"(a3), "r"(b0), "r"(b1));
}

// out[b, n*32+cc, h, w] = sum_{c<16,kh,kw} x[b,(4cc-c)&127,(h-kh)&31,(w-kw)&31] * W[n,c,kh,kw]
// CTA = (g, b). Warp = one h row per pass. M-row r of each m16 tile maps to
// w = 2r (r<8) / 2(r-8)+1 (r>=8), so each thread's A window is 10 contiguous
// words (5 LDS.64). K = 16-channel band per jc, 2 k8 steps; 81 taps in registers.
__global__ __launch_bounds__(512, 1)
void fconv_mma(const float* __restrict__ x, const float* __restrict__ w,
               float* __restrict__ out)
{
    extern __shared__ u32 sm[];
    u32* xs = sm;                 // [c<28][h<32][j<40], j = w + 8 (circular halo)
    u32* Bs = sm + BW_OFF;        // pairs: [tap][ks][tq][n][2] = (B[8ks+tq][n], B[8ks+tq+4][n])

    const int t = threadIdx.x, g = blockIdx.x, b = blockIdx.y;
    const int chb = (16 * g + 113) & 127;          // (16g - 15) mod 128
    const float* xb = x + (size_t)b * 131072;

    // ---- stage x as tf32, halo'd rows of 40 ----
    for (int i = t; i < 28 * 1280; i += 512) {
        int c = i / 1280, r = i % 1280, hh = r / 40, j = r % 40;
        xs[c * XP + hh * 40 + j] =
            f2t(xb[((chb + c) & 127) * 1024 + hh * 32 + ((j + 24) & 31)]);
    }
    // ---- stage B pairs ----
    for (int i = t; i < 10368; i += 512) {
        int tap = i >> 7, r = i & 127;
        int ks = r >> 6, r2 = r & 63, tq = r2 >> 4, r3 = r2 & 15;
        int n = r3 >> 1, half = r3 & 1;
        int k = 8 * ks + tq + 4 * half;            // c = 15-k in 0..15
        Bs[i] = f2t(w[n * 1296 + (15 - k) * 81 + tap]);
    }
    __syncthreads();

    const int lane = t & 31, wid = t >> 5, gq = lane >> 2, tq = lane & 3;
    const u64* Bs64 = (const u64*)Bs;

    #pragma unroll 1
    for (int pass = 0; pass < 2; ++pass) {
        const int h = wid + 16 * pass;
        float acc[2][4][4];
        #pragma unroll
        for (int mt = 0; mt < 2; ++mt)
            #pragma unroll
            for (int jc = 0; jc < 4; ++jc)
                #pragma unroll
                for (int q = 0; q < 4; ++q) acc[mt][jc][q] = 0.f;

        #pragma unroll 1
        for (int kh = 0; kh < 9; ++kh) {
            const int row = (h - kh) & 31;
            const u32* xrow = xs + row * 40 + 2 * gq;   // + ch*XP + 16*mt

            // CH[buf][mt][0..9] = x[ch][row][halo j = 2gq+16mt + j], chunk c -> buf c%3
            u32 CH[3][2][10];
            #pragma unroll
            for (int ci = 0; ci < 2; ++ci) {
                const u32* p = xrow + (4 * ci + tq) * XP;
                #pragma unroll
                for (int mt = 0; mt < 2; ++mt)
                    #pragma unroll
                    for (int q = 0; q < 5; ++q) {
                        uint2 v = *(const uint2*)(p + 16 * mt + 2 * q);
                        CH[ci][mt][2 * q] = v.x; CH[ci][mt][2 * q + 1] = v.y;
                    }
            }

            #pragma unroll
            for (int i = 0; i < 6; ++i) {
                if (i < 5) {   // prefetch chunk i+2 into buf (i+2)%3 (holds dead chunk i-1)
                    const u32* p = xrow + (4 * (i + 2) + tq) * XP;
                    #pragma unroll
                    for (int mt = 0; mt < 2; ++mt)
                        #pragma unroll
                        for (int q = 0; q < 5; ++q) {
                            uint2 v = *(const uint2*)(p + 16 * mt + 2 * q);
                            CH[(i + 2) % 3][mt][2 * q] = v.x;
                            CH[(i + 2) % 3][mt][2 * q + 1] = v.y;
                        }
                }
                const int lob = i % 3, hib = (i + 1) % 3;
                #pragma unroll
                for (int kw = 0; kw < 9; ++kw) {
                    const int tap = kh * 9 + kw;
                    #pragma unroll
                    for (int u = 0; u < 2; ++u) {
                        // (jc = i, ks = 0) valid i<4 ; (jc = i-2, ks = 1) valid i>=2
                        if ((u == 0 && i < 4) || (u == 1 && i >= 2)) {
                            const int jc = (u == 0) ? i : i - 2;
                            u64 bb = Bs64[((tap * 2 + u) * 4 + tq) * 8 + gq];
                            u32 b0 = (u32)bb, b1 = (u32)(bb >> 32);
                            #pragma unroll
                            for (int mt = 0; mt < 2; ++mt)
                                mma8(acc[mt][jc][0], acc[mt][jc][1],
                                     acc[mt][jc][2], acc[mt][jc][3],
                                     CH[lob][mt][8 - kw], CH[lob][mt][9 - kw],
                                     CH[hib][mt][8 - kw], CH[hib][mt][9 - kw],
                                     b0, b1);
                        }
                    }
                }
            }
        }

        // ---- store: thread gq rows -> w = 2gq+16mt (+1); cols 2tq, 2tq+1 ----
        #pragma unroll
        for (int mt = 0; mt < 2; ++mt)
            #pragma unroll
            for (int jc = 0; jc < 4; ++jc) {
                const int cc = 4 * g + jc;
                const int w0 = 2 * gq + 16 * mt;
                #pragma unroll
                for (int d = 0; d < 2; ++d) {
                    const int ch = (2 * tq + d) * 32 + cc;
                    float2 s = make_float2(acc[mt][jc][d], acc[mt][jc][2 + d]);
                    *(float2*)(out + (size_t)b * 262144 + (size_t)ch * 1024
                               + h * 32 + w0) = s;
                }
            }
    }
}

extern "C" void kernel_launch(void* const* d_in, const int* in_sizes, int n_in,
                              void* d_out, int out_size)
{
    const float* x = (const float*)d_in[0];   // (32,128,32,32) f32
    const float* w = (const float*)d_in[1];   // (8,16,9,9) f32
    float* out = (float*)d_out;               // (32,256,32,32) f32

    cudaFuncSetAttribute(fconv_mma,
                         cudaFuncAttributeMaxDynamicSharedMemorySize, SMEM_BYTES);
    dim3 grid(8, 32);
    fconv_mma<<<grid, 512, SMEM_BYTES>>>(x, w, out);
}